// round 12
// baseline (speedup 1.0000x reference)
#include <cuda_runtime.h>

#define B_SZ   8192
#define IN_SZ  64
#define OUT_SZ 64
#define NS     8
#define NB     20
#define NI     19

#define WARPS_PER_BLK 8     // one warp = one batch row
#define LN2f  0.69314718055994530942f
#define L2Ef  1.44269504088896340736f

// Precomputed per-(o,i) parameter tables, [i*OUT + o] layout (coalesced over o).
// PA = { b1*scale*ln2, b2*ln2, b3*log2e, b4 }
// PB = { b5..b8 * scale },  scale = softplus(raw_gamma)/OUT
__device__ float4 g_PA[IN_SZ * OUT_SZ];
__device__ float4 g_PB[IN_SZ * OUT_SZ];

__device__ __forceinline__ float ex2f(float x) {
    float y; asm("ex2.approx.ftz.f32 %0, %1;" : "=f"(y) : "f"(x)); return y;
}
__device__ __forceinline__ float lg2f(float x) {
    float y; asm("lg2.approx.ftz.f32 %0, %1;" : "=f"(y) : "f"(x)); return y;
}

__global__ void prep_kernel(const float* __restrict__ raw_gamma,
                            const float* __restrict__ w,
                            const float* __restrict__ breaks,
                            const float* __restrict__ coefs,
                            const float* __restrict__ mu_p,
                            const float* __restrict__ sigma_p)
{
    int tid = blockIdx.x * blockDim.x + threadIdx.x;
    if (tid < IN_SZ * OUT_SZ) {
        int o = tid / IN_SZ;
        int i = tid % IN_SZ;

        float mu = mu_p[0];
        float sigma = sigma_p[0];

        float wv = w[o * IN_SZ + i];
        wv = fminf(fmaxf(wv, -5.5f), 37.9f);
        float wn = (wv - mu) / sigma;

        float b[NS];
#pragma unroll
        for (int s = 0; s < NS; s++) {
            const float* br = breaks + s * NB;
            float lo = br[0];
            float hi = br[NB - 1] - 1e-6f;
            float wl = fminf(fmaxf(wn, lo), hi);
            // searchsorted(br, wl, 'left') - 1  ==  (#elements < wl) - 1
            int idx = -1;
#pragma unroll
            for (int j = 0; j < NB; j++) idx += (br[j] < wl) ? 1 : 0;
            idx = max(0, min(idx, NI - 1));
            const float* cf = coefs + (s * NI + idx) * 4;
            float t = wl - br[idx];
            b[s] = ((cf[0] * t + cf[1]) * t + cf[2]) * t + cf[3];
        }

        float g = raw_gamma[o * IN_SZ + i];
        float sp = fmaxf(g, 0.0f) + log1pf(__expf(-fabsf(g)));   // stable softplus
        float scale = sp * (1.0f / OUT_SZ);

        g_PA[i * OUT_SZ + o] = make_float4(b[0] * scale * LN2f,  // b1'
                                           b[1] * LN2f,          // b2'
                                           b[2] * L2Ef,          // b3'
                                           b[3]);                // b4
        g_PB[i * OUT_SZ + o] = make_float4(b[4] * scale, b[5] * scale,
                                           b[6] * scale, b[7] * scale);
    }
    // PDL flush: table writes are visible to the dependent grid after its wait.
    asm volatile("griddepcontrol.launch_dependents;");
}

// One live evaluation: 5 MUFU + 10 fma-pipe ops.
__device__ __forceinline__ void eval1(float xv, float4 pa, float4 pb, float& acc)
{
    float e     = ex2f(pa.z * xv);           // exp(b3*x) == 2^(b3' x)
    float u     = e - 1.0f;
    float p     = ex2f(pa.w * lg2f(u));      // u^b4
    float L1    = lg2f(1.0f + p);            // log1p/ln2
    float inner = fmaf(pa.y, L1, 1.0f);      // 1 + b2*log1p
    float L2    = lg2f(inner);
    float h     = fmaf(pb.w, xv, pb.z);
    h           = fmaf(h, xv, pb.y);
    h           = fmaf(h, xv, pb.x);
    acc         = fmaf(xv, h, acc);
    acc         = fmaf(pa.x, L2, acc);       // + b1*scale*ln(inner)
}

// block = 256 threads = 8 warps; warp = one batch row, lane covers o=lane, lane+32.
// Phase 1 (register-resident): load row, ballot-compact live i's into the warp's
// private smem list. Phase 2: branchless loop, 2 evals/thread/entry.
__global__ __launch_bounds__(32 * WARPS_PER_BLK, 6)
void main_kernel(const float* __restrict__ x, float* __restrict__ out)
{
    __shared__ float2 comp[WARPS_PER_BLK][IN_SZ];   // (x, float-bits of i*64)

    const int lane = threadIdx.x & 31;
    const int wrp  = threadIdx.x >> 5;              // 0..7 = row within block
    const int row  = blockIdx.x * WARPS_PER_BLK + wrp;

    // row load: 2 coalesced LDG.32 per lane
    float v0 = fmaxf(x[row * IN_SZ + lane], 0.0f);
    float v1 = fmaxf(x[row * IN_SZ + lane + 32], 0.0f);

    // warp-private order-preserving compaction
    unsigned m0 = __ballot_sync(0xffffffffu, v0 > 0.0f);
    unsigned m1 = __ballot_sync(0xffffffffu, v1 > 0.0f);
    int n0 = __popc(m0);
    const int n = n0 + __popc(m1);
    unsigned below = (1u << lane) - 1u;
    if (v0 > 0.0f)
        comp[wrp][__popc(m0 & below)] = make_float2(v0, __int_as_float(lane << 6));
    if (v1 > 0.0f)
        comp[wrp][n0 + __popc(m1 & below)] =
            make_float2(v1, __int_as_float((lane + 32) << 6));
    __syncwarp();

    // Wait for prep's table writes (PDL dependency).
    asm volatile("griddepcontrol.wait;");

    float acc0 = 0.0f, acc1 = 0.0f;

#pragma unroll 2
    for (int c = 0; c < n; c++) {
        float2 e = comp[wrp][c];                // broadcast LDS.64
        float xv = e.x;
        int ib   = __float_as_int(e.y);         // i*64
        float4 pa0 = g_PA[ib + lane];
        float4 pb0 = g_PB[ib + lane];
        float4 pa1 = g_PA[ib + lane + 32];
        float4 pb1 = g_PB[ib + lane + 32];
        eval1(xv, pa0, pb0, acc0);
        eval1(xv, pa1, pb1, acc1);
    }

    out[row * OUT_SZ + lane]      = acc0;
    out[row * OUT_SZ + lane + 32] = acc1;
}

extern "C" void kernel_launch(void* const* d_in, const int* in_sizes, int n_in,
                              void* d_out, int out_size)
{
    // metadata order: x, raw_gamma, w, breaks, coefs, mu_detuning, sigma_detuning
    const float* x         = (const float*)d_in[0];
    const float* raw_gamma = (const float*)d_in[1];
    const float* w         = (const float*)d_in[2];
    const float* breaks    = (const float*)d_in[3];
    const float* coefs     = (const float*)d_in[4];
    const float* mu        = (const float*)d_in[5];
    const float* sigma     = (const float*)d_in[6];
    float* out = (float*)d_out;

    prep_kernel<<<32, 128>>>(raw_gamma, w, breaks, coefs, mu, sigma);

    // PDL: main's launch ramp + x-load + compaction overlap prep's execution.
    cudaLaunchConfig_t cfg = {};
    cfg.gridDim  = dim3(B_SZ / WARPS_PER_BLK);
    cfg.blockDim = dim3(32 * WARPS_PER_BLK);
    cfg.dynamicSmemBytes = 0;
    cudaLaunchAttribute attrs[1];
    attrs[0].id = cudaLaunchAttributeProgrammaticStreamSerialization;
    attrs[0].val.programmaticStreamSerializationAllowed = 1;
    cfg.attrs = attrs;
    cfg.numAttrs = 1;
    cudaLaunchKernelEx(&cfg, main_kernel, x, out);
}